// round 15
// baseline (speedup 1.0000x reference)
#include <cuda_runtime.h>
#include <cuda_fp16.h>
#include <cstdint>
#include <math.h>

// Problem constants
#define B_ 4
#define T_ 2048
#define C_ 1024
#define H_ 16
#define D_ 64
#define M_ (B_*T_)   // 8192
#define N_ 1024
#define K_ 1024

// Scratch (device globals: allocation-free). All single fp16 planes.
__device__ __half g_x16[(size_t)M_ * C_];            // x
__device__ __half g_y16[(size_t)M_ * C_];            // attention out
__device__ __half g_w16[3u * 1024u * 1024u];         // Wq|Wk|Wv transposed [N,K]
__device__ __half g_wo16[1024u * 1024u];             // Wo transposed [N,K]
// fp16 attention operand planes [B,H,T,D]
__device__ __half g_q16[(size_t)M_ * C_];            // Q prescaled by exp(ls)*0.125*log2e
__device__ __half g_k16[(size_t)M_ * C_];            // K
__device__ __half g_v16[(size_t)M_ * C_];            // V

__device__ __forceinline__ uint32_t smem_u32(const void* p) {
    uint32_t a;
    asm("{ .reg .u64 t; cvta.to.shared.u64 t, %1; cvt.u32.u64 %0, t; }" : "=r"(a) : "l"(p));
    return a;
}

#define LDSM4(r0, r1, r2, r3, a) \
    asm volatile("ldmatrix.sync.aligned.m8n8.x4.shared.b16 {%0,%1,%2,%3}, [%4];" \
        : "=r"(r0), "=r"(r1), "=r"(r2), "=r"(r3) : "r"(a))
#define LDSM4T(r0, r1, r2, r3, a) \
    asm volatile("ldmatrix.sync.aligned.m8n8.x4.trans.shared.b16 {%0,%1,%2,%3}, [%4];" \
        : "=r"(r0), "=r"(r1), "=r"(r2), "=r"(r3) : "r"(a))

#define MMA_F16(c, a, b0, b1) \
    asm volatile("mma.sync.aligned.m16n8k16.row.col.f32.f16.f16.f32 " \
        "{%0,%1,%2,%3}, {%4,%5,%6,%7}, {%8,%9}, {%0,%1,%2,%3};" \
        : "+f"((c)[0]), "+f"((c)[1]), "+f"((c)[2]), "+f"((c)[3]) \
        : "r"((a)[0]), "r"((a)[1]), "r"((a)[2]), "r"((a)[3]), "r"(b0), "r"(b1))

#define CP16(dst, src) \
    asm volatile("cp.async.cg.shared.global [%0], [%1], 16;" :: "r"(dst), "l"(src))
#define CPCOMMIT() asm volatile("cp.async.commit_group;" ::: "memory")
#define CPWAIT(n)  asm volatile("cp.async.wait_group %0;" :: "n"(n) : "memory")

#define ONE2 0x3C003C00u   // half2(1.0, 1.0)

__device__ __forceinline__ uint32_t ex2h2(uint32_t x) {
    uint32_t r;
    asm("ex2.approx.f16x2 %0, %1;" : "=r"(r) : "r"(x));
    return r;
}
__device__ __forceinline__ uint32_t pack_h2(float a, float b) {
    __half2 h = __floats2half2_rn(a, b);
    return *(uint32_t*)&h;
}

// ---------------------------------------------------------------------------
// convert x: fp32 -> single fp16
// ---------------------------------------------------------------------------
__global__ void __launch_bounds__(256) cvtx_kernel(const float* __restrict__ in) {
    int i = (blockIdx.x * 256 + threadIdx.x) * 4;
    float4 v = *(const float4*)(in + i);
    ((__half2*)(g_x16 + i))[0] = __floats2half2_rn(v.x, v.y);
    ((__half2*)(g_x16 + i))[1] = __floats2half2_rn(v.z, v.w);
}

// ---------------------------------------------------------------------------
// transpose weights: Wq/Wk/Wv -> g_w16, Wo -> g_wo16, all single fp16 [N,K]
// ---------------------------------------------------------------------------
__global__ void __launch_bounds__(256) tsplitw_kernel(
    const float* __restrict__ W0, const float* __restrict__ W1,
    const float* __restrict__ W2, const float* __restrict__ W3)
{
    __shared__ float tile[32][33];
    const int widx = blockIdx.z;
    const float* in = (widx == 0) ? W0 : (widx == 1) ? W1 : (widx == 2) ? W2 : W3;
    __half* o16 = (widx < 3) ? (g_w16 + (size_t)widx * 1024 * 1024) : g_wo16;
    int tx = threadIdx.x, ty = threadIdx.y;
    int x = blockIdx.x * 32 + tx, y0 = blockIdx.y * 32;
#pragma unroll
    for (int j = 0; j < 32; j += 8) tile[ty + j][tx] = in[(size_t)(y0 + ty + j) * 1024 + x];
    __syncthreads();
    int x2 = blockIdx.y * 32 + tx, y2 = blockIdx.x * 32;
#pragma unroll
    for (int j = 0; j < 32; j += 8)
        o16[(size_t)(y2 + ty + j) * 1024 + x2] = __float2half(tile[tx][ty + j]);
}

// ---------------------------------------------------------------------------
// Unified fp16 GEMM, 1 MMA/tile, k-step 64 per stage (half the barriers).
// Planes 128x72 fp16 (A | B), 2 stages = 72KB, 2 CTAs/SM.
// mode 0 (QKV, N=3072): scatter Q(prescaled)/K/V single fp16 [B,H,T,D].
// mode 1 (out, N=1024): fp32 row-major Cext.
// ---------------------------------------------------------------------------
#define GAST 72                      // row stride (elems)
#define GPL (128 * GAST * 2)         // 18432 bytes per plane
#define GSTG (2 * GPL)               // 36864 per stage: A | B
#define NT_K2 16                     // 1024 / 64

__global__ void __launch_bounds__(256, 2) gemm16(
    const __half* __restrict__ Ap, const __half* __restrict__ Bp,
    float* __restrict__ Cext, const float* __restrict__ ls, int mode)
{
    extern __shared__ char gsm[];
    const uint32_t sb = smem_u32(gsm);
    const int tid = threadIdx.x;
    const int warp = tid >> 5, lane = tid & 31;
    const int bm = blockIdx.y * 128, bn = blockIdx.x * 128;
    const int wm = (warp >> 2) * 64, wn = (warp & 3) * 32;

    float acc[4][4][4];
#pragma unroll
    for (int i = 0; i < 4; i++)
#pragma unroll
        for (int j = 0; j < 4; j++)
#pragma unroll
            for (int r = 0; r < 4; r++) acc[i][j][r] = 0.f;

    // loader: row = tid>>1 (0..127), col chunk = (tid&1)*32 (4 x CP16 per plane)
    const int lr = tid >> 1, lc = (tid & 1) << 5;
    const size_t aoff = (size_t)(bm + lr) * K_ + lc;
    const size_t boff = (size_t)(bn + lr) * K_ + lc;
    const uint32_t drow = sb + (uint32_t)lr * (GAST * 2) + (uint32_t)lc * 2;

#define GISSUE(st, kt) do { \
    uint32_t d = drow + (uint32_t)(st) * GSTG; \
    size_t k0 = (size_t)(kt) * 64; \
    CP16(d,              Ap + aoff + k0); \
    CP16(d + 16,         Ap + aoff + k0 + 8); \
    CP16(d + 32,         Ap + aoff + k0 + 16); \
    CP16(d + 48,         Ap + aoff + k0 + 24); \
    CP16(d + GPL,        Bp + boff + k0); \
    CP16(d + GPL + 16,   Bp + boff + k0 + 8); \
    CP16(d + GPL + 32,   Bp + boff + k0 + 16); \
    CP16(d + GPL + 48,   Bp + boff + k0 + 24); \
} while (0)

    GISSUE(0, 0);
    CPCOMMIT();

    const uint32_t aAddr = (uint32_t)((wm + (lane & 15)) * (GAST * 2) + (((lane >> 4) << 3)) * 2);
    const uint32_t bAddr = (uint32_t)(GPL + (wn + ((lane >> 4) << 3) + (lane & 7)) * (GAST * 2) + ((lane & 8)) * 2);

    for (int kt = 0; kt < NT_K2; ++kt) {
        {
            int nt = kt + 1;
            if (nt < NT_K2) GISSUE(nt & 1, nt);
            CPCOMMIT();
        }
        CPWAIT(1);
        __syncthreads();
        const uint32_t stb = sb + (uint32_t)(kt & 1) * GSTG;

#pragma unroll
        for (int kk = 0; kk < 4; kk++) {
            const uint32_t ko = (uint32_t)(kk * 32);
            uint32_t ah[4][4];
#pragma unroll
            for (int i = 0; i < 4; i++) {
                uint32_t ad = stb + aAddr + (uint32_t)(i * 16 * GAST * 2) + ko;
                LDSM4(ah[i][0], ah[i][1], ah[i][2], ah[i][3], ad);
            }
#pragma unroll
            for (int jb = 0; jb < 2; jb++) {
                uint32_t bh[4];
                uint32_t bd = stb + bAddr + (uint32_t)(jb * 16 * GAST * 2) + ko;
                LDSM4(bh[0], bh[1], bh[2], bh[3], bd);
#pragma unroll
                for (int i = 0; i < 4; i++) {
                    MMA_F16(acc[i][2*jb],   ah[i], bh[0], bh[1]);
                    MMA_F16(acc[i][2*jb+1], ah[i], bh[2], bh[3]);
                }
            }
        }
        __syncthreads();
    }

    const int gr = lane >> 2, gc = (lane & 3) * 2;
    if (mode == 0) {
        const int sel = (bn + wn) >> 10;            // 0=Q 1=K 2=V (warp-constant)
        const int hh = ((bn + wn) >> 6) & 15;
        const float qs = (sel == 0) ? __expf(ls[hh]) * 0.125f * 1.4426950408889634f : 1.f;
        __half* Dst = (sel == 0) ? g_q16 : (sel == 1) ? g_k16 : g_v16;
#pragma unroll
        for (int i = 0; i < 4; i++)
#pragma unroll
            for (int j = 0; j < 4; j++) {
                int m0 = bm + wm + i * 16 + gr;
                int n0 = bn + wn + j * 8 + gc;
                int d = n0 & 63;
#pragma unroll
                for (int hrow = 0; hrow < 2; hrow++) {
                    int m = m0 + hrow * 8;
                    int b = m >> 11, t = m & (T_ - 1);
                    size_t idx = ((size_t)((b * H_ + hh) * T_ + t)) * D_ + d;
                    *(uint32_t*)(Dst + idx) =
                        pack_h2(acc[i][j][hrow*2] * qs, acc[i][j][hrow*2+1] * qs);
                }
            }
    } else {
#pragma unroll
        for (int i = 0; i < 4; i++)
#pragma unroll
            for (int j = 0; j < 4; j++) {
                int m0 = bm + wm + i * 16 + gr;
                int n0 = bn + wn + j * 8 + gc;
                *(float2*)&Cext[(size_t)m0 * N_ + n0] = make_float2(acc[i][j][0], acc[i][j][1]);
                *(float2*)&Cext[(size_t)(m0 + 8) * N_ + n0] = make_float2(acc[i][j][2], acc[i][j][3]);
            }
    }
}

// ---------------------------------------------------------------------------
// Flash attention v9: 128-key stages (2 x 64-key sub-blocks per stage),
// half the barriers. f16x2 softmax + l via ones-column MMA.
// 256 threads, 128 q-rows/CTA. QK^T = 1 MMA; PV = 1 MMA.
// ---------------------------------------------------------------------------
#define AST 72
#define PL128A (128 * AST * 2)   // 18432 bytes per plane (128 keys)
#define PL16  (16 * AST * 2)     // 2304
#define HALF_B (64 * AST * 2)    // 9216: 64-key sub-block offset
#define STAGE_B (2 * PL128A)     // 36864: K | V
#define S_NULL  (2 * STAGE_B)    // 73728
#define S_NK  (S_NULL)
#define S_NV  (S_NULL + PL16)
#define S_ATT_TOTAL (S_NULL + 2*PL16)   // 78336

__global__ void __launch_bounds__(256, 2) attn_mma(
    const float* __restrict__ nullk, const float* __restrict__ nullv)
{
    extern __shared__ char sm[];
    const uint32_t sb = smem_u32(sm);
    const int bh = blockIdx.y, h = bh & 15;
    const int qblk = (T_ / 128 - 1) - blockIdx.x;   // longest first
    const int qbase = qblk * 128;
    const int tid = threadIdx.x, warp = tid >> 5, lane = tid & 31;
    const int wm = warp * 16;

    // null tiles: 16 x 64, row 0 real
    for (int i = tid; i < 1024; i += 256) {
        int r = i >> 6, d = i & 63;
        float kvk = (r == 0) ? nullk[h * 64 + d] : 0.f;
        float kvv = (r == 0) ? nullv[h * 64 + d] : 0.f;
        *(__half*)(sm + S_NK + (r * AST + d) * 2) = __float2half(kvk);
        *(__half*)(sm + S_NV + (r * AST + d) * 2) = __float2half(kvv);
    }

    // Q fragments: direct LDG from prescaled fp16 plane
    uint32_t qf[4][4];
    {
        const size_t qrow0 = (size_t)bh * T_ + qbase + wm + (lane >> 2);
        const int cc = (lane & 3) * 2;
#pragma unroll
        for (int kk = 0; kk < 4; kk++) {
#pragma unroll
            for (int rg = 0; rg < 4; rg++) {
                int roff = (rg & 1) * 8;
                int col = kk * 16 + cc + (rg >> 1) * 8;
                qf[kk][rg] = *(const uint32_t*)(g_q16 + (qrow0 + roff) * D_ + col);
            }
        }
    }

    float o[8][4];
#pragma unroll
    for (int j = 0; j < 8; j++)
#pragma unroll
        for (int r = 0; r < 4; r++) o[j][r] = 0.f;
    float lacc[4] = {0.f, 0.f, 0.f, 0.f};   // l via P @ ones

    const int qmin_w = qbase + wm;
    const int qmax_w = qbase + wm + 15;
    const int nkb2 = qblk + 1;               // 128-key blocks

    // K/V cp.async staging map: row = tid>>1 (0..127), col chunk = (tid&1)*32
    const int sr = tid >> 1, scol = (tid & 1) << 5;
    const uint32_t doff = (uint32_t)((sr * AST + scol) * 2);
    const size_t gbase0 = ((size_t)bh * T_ + sr) * D_ + scol;

#define AISS(st, kb_) do { \
    size_t base_ = gbase0 + (size_t)(kb_) * 128 * D_; \
    uint32_t d_ = sb + (uint32_t)(st) * STAGE_B + doff; \
    CP16(d_,                   g_k16 + base_); \
    CP16(d_ + 16,              g_k16 + base_ + 8); \
    CP16(d_ + 32,              g_k16 + base_ + 16); \
    CP16(d_ + 48,              g_k16 + base_ + 24); \
    CP16(d_ + PL128A,          g_v16 + base_); \
    CP16(d_ + PL128A + 16,     g_v16 + base_ + 8); \
    CP16(d_ + PL128A + 32,     g_v16 + base_ + 16); \
    CP16(d_ + PL128A + 48,     g_v16 + base_ + 24); \
} while (0)

    AISS(0, 0);
    CPCOMMIT();

    for (int kb2 = 0; kb2 < nkb2; kb2++) {
        __syncthreads();                 // everyone done reading the other stage
        if (kb2 + 1 < nkb2) AISS((kb2 + 1) & 1, kb2 + 1);
        CPCOMMIT();
        CPWAIT(1);
        __syncthreads();                 // stage kb2 visible to all
        const uint32_t stbase = sb + (uint32_t)(kb2 & 1) * STAGE_B;

#pragma unroll
        for (int half = 0; half < 2; half++) {
            const int kbase = kb2 * 128 + half * 64;
            if (kbase > qmax_w) continue;  // warp fully below diagonal
            const uint32_t stb = stbase + (uint32_t)half * HALF_B;

            // S = Qs K^T   (1 MMA per acc)
            float s[8][4];
#pragma unroll
            for (int j = 0; j < 8; j++)
#pragma unroll
                for (int r = 0; r < 4; r++) s[j][r] = 0.f;
#pragma unroll
            for (int kk = 0; kk < 4; kk++) {
#pragma unroll
                for (int jb = 0; jb < 4; jb++) {
                    uint32_t kf[4];
                    uint32_t bd = stb + (uint32_t)((jb * 16 + ((lane >> 4) << 3) + (lane & 7)) * AST
                                + kk * 16 + (lane & 8)) * 2;
                    LDSM4(kf[0], kf[1], kf[2], kf[3], bd);
                    MMA_F16(s[2*jb],   qf[kk], kf[0], kf[1]);
                    MMA_F16(s[2*jb+1], qf[kk], kf[2], kf[3]);
                }
            }

            // causal mask (diagonal warp-block only)
            if (kbase + 63 > qmin_w) {
                const int q0 = qmin_w + (lane >> 2), q1 = q0 + 8;
#pragma unroll
                for (int j = 0; j < 8; j++) {
                    int c = kbase + j * 8 + ((lane & 3) << 1);
                    if (c     > q0) s[j][0] = -1e30f;
                    if (c + 1 > q0) s[j][1] = -1e30f;
                    if (c     > q1) s[j][2] = -1e30f;
                    if (c + 1 > q1) s[j][3] = -1e30f;
                }
            }

            // P = exp2(S) in f16x2; l += P @ 1 (tensor pipe)
            uint32_t ph[4][4];
#pragma unroll
            for (int kk = 0; kk < 4; kk++) {
                ph[kk][0] = ex2h2(pack_h2(s[2*kk][0],   s[2*kk][1]));
                ph[kk][1] = ex2h2(pack_h2(s[2*kk][2],   s[2*kk][3]));
                ph[kk][2] = ex2h2(pack_h2(s[2*kk+1][0], s[2*kk+1][1]));
                ph[kk][3] = ex2h2(pack_h2(s[2*kk+1][2], s[2*kk+1][3]));
                MMA_F16(lacc, ph[kk], ONE2, ONE2);
            }

            // O += P V   (1 MMA per acc)
#pragma unroll
            for (int kk = 0; kk < 4; kk++) {
#pragma unroll
                for (int g = 0; g < 4; g++) {
                    uint32_t vh[4];
                    uint32_t vd = stb + PL128A + (uint32_t)((kk * 16 + (lane & 15)) * AST
                                + g * 16 + ((lane >> 4) << 3)) * 2;
                    LDSM4T(vh[0], vh[1], vh[2], vh[3], vd);
                    MMA_F16(o[2*g],   ph[kk], vh[0], vh[1]);
                    MMA_F16(o[2*g+1], ph[kk], vh[2], vh[3]);
                }
            }
        }
    }

    // null-KV block (16 padded cols, col 0 real)
    {
        float s[2][4];
#pragma unroll
        for (int j = 0; j < 2; j++)
#pragma unroll
            for (int r = 0; r < 4; r++) s[j][r] = 0.f;
#pragma unroll
        for (int kk = 0; kk < 4; kk++) {
            uint32_t kf[4];
            uint32_t bd = sb + S_NK + (uint32_t)((((lane >> 4) << 3) + (lane & 7)) * AST
                        + kk * 16 + (lane & 8)) * 2;
            LDSM4(kf[0], kf[1], kf[2], kf[3], bd);
            MMA_F16(s[0], qf[kk], kf[0], kf[1]);
            MMA_F16(s[1], qf[kk], kf[2], kf[3]);
        }
#pragma unroll
        for (int j = 0; j < 2; j++) {
            int c = j * 8 + ((lane & 3) << 1);
            if (c != 0) s[j][0] = -1e30f;
            s[j][1] = -1e30f;
            if (c != 0) s[j][2] = -1e30f;
            s[j][3] = -1e30f;
        }
        uint32_t ph[4];
        ph[0] = ex2h2(pack_h2(s[0][0], s[0][1]));
        ph[1] = ex2h2(pack_h2(s[0][2], s[0][3]));
        ph[2] = ex2h2(pack_h2(s[1][0], s[1][1]));
        ph[3] = ex2h2(pack_h2(s[1][2], s[1][3]));
        MMA_F16(lacc, ph, ONE2, ONE2);
#pragma unroll
        for (int g = 0; g < 4; g++) {
            uint32_t vh[4];
            uint32_t vd = sb + S_NV + (uint32_t)((lane & 15) * AST + g * 16 + ((lane >> 4) << 3)) * 2;
            LDSM4T(vh[0], vh[1], vh[2], vh[3], vd);
            MMA_F16(o[2*g],   ph, vh[0], vh[1]);
            MMA_F16(o[2*g+1], ph, vh[2], vh[3]);
        }
    }

    // finalize: l comes straight from lacc (row sums, replicated per quad)
    const float i0 = 1.f / lacc[0], i1 = 1.f / lacc[2];
    const int b = bh >> 4;
    const int t0 = qbase + wm + (lane >> 2), t1 = t0 + 8;
    const int cb = h * 64 + ((lane & 3) << 1);
#pragma unroll
    for (int j = 0; j < 8; j++) {
        int cc = cb + j * 8;
        *(uint32_t*)(g_y16 + (size_t)(b * T_ + t0) * C_ + cc) = pack_h2(o[j][0] * i0, o[j][1] * i0);
        *(uint32_t*)(g_y16 + (size_t)(b * T_ + t1) * C_ + cc) = pack_h2(o[j][2] * i1, o[j][3] * i1);
    }
}

// ---------------------------------------------------------------------------
// kernel_launch
// Inputs: x, Wq, Wk, Wv, Wo, null_k, null_v, logit_scale
// ---------------------------------------------------------------------------
extern "C" void kernel_launch(void* const* d_in, const int* in_sizes, int n_in,
                              void* d_out, int out_size) {
    const float* x  = (const float*)d_in[0];
    const float* Wq = (const float*)d_in[1];
    const float* Wk = (const float*)d_in[2];
    const float* Wv = (const float*)d_in[3];
    const float* Wo = (const float*)d_in[4];
    const float* nk = (const float*)d_in[5];
    const float* nv = (const float*)d_in[6];
    const float* ls = (const float*)d_in[7];
    float* out = (float*)d_out;

    __half *x16, *y16, *w16, *wo16;
    cudaGetSymbolAddress((void**)&x16, g_x16);
    cudaGetSymbolAddress((void**)&y16, g_y16);
    cudaGetSymbolAddress((void**)&w16, g_w16);
    cudaGetSymbolAddress((void**)&wo16, g_wo16);

    const int GEMM_SMEM = 2 * GSTG;       // 73728
    cudaFuncSetAttribute(gemm16, cudaFuncAttributeMaxDynamicSharedMemorySize, GEMM_SMEM);
    cudaFuncSetAttribute(attn_mma, cudaFuncAttributeMaxDynamicSharedMemorySize, S_ATT_TOTAL);

    cvtx_kernel<<<(M_ * C_) / (256 * 4), 256>>>(x);
    tsplitw_kernel<<<dim3(32, 32, 4), dim3(32, 8)>>>(Wq, Wk, Wv, Wo);

    gemm16<<<dim3(24, 64), 256, GEMM_SMEM>>>(x16, w16, nullptr, ls, 0);

    attn_mma<<<dim3(T_ / 128, B_ * H_), 256, S_ATT_TOTAL>>>(nk, nv);

    gemm16<<<dim3(8, 64), 256, GEMM_SMEM>>>(y16, wo16, out, ls, 1);
}

// round 16
// speedup vs baseline: 1.1429x; 1.1429x over previous
#include <cuda_runtime.h>
#include <cuda_fp16.h>
#include <cstdint>
#include <math.h>

// Problem constants
#define B_ 4
#define T_ 2048
#define C_ 1024
#define H_ 16
#define D_ 64
#define M_ (B_*T_)   // 8192
#define N_ 1024
#define K_ 1024

// Scratch (device globals: allocation-free). All single fp16 planes.
__device__ __half g_x16[(size_t)M_ * C_];            // x
__device__ __half g_y16[(size_t)M_ * C_];            // attention out
__device__ __half g_w16[3u * 1024u * 1024u];         // Wq|Wk|Wv transposed [N,K]
__device__ __half g_wo16[1024u * 1024u];             // Wo transposed [N,K]
// fp16 attention operand planes [B,H,T,D]
__device__ __half g_q16[(size_t)M_ * C_];            // Q prescaled by exp(ls)*0.125*log2e
__device__ __half g_k16[(size_t)M_ * C_];            // K
__device__ __half g_v16[(size_t)M_ * C_];            // V

__device__ __forceinline__ uint32_t smem_u32(const void* p) {
    uint32_t a;
    asm("{ .reg .u64 t; cvta.to.shared.u64 t, %1; cvt.u32.u64 %0, t; }" : "=r"(a) : "l"(p));
    return a;
}

#define LDSM4(r0, r1, r2, r3, a) \
    asm volatile("ldmatrix.sync.aligned.m8n8.x4.shared.b16 {%0,%1,%2,%3}, [%4];" \
        : "=r"(r0), "=r"(r1), "=r"(r2), "=r"(r3) : "r"(a))
#define LDSM4T(r0, r1, r2, r3, a) \
    asm volatile("ldmatrix.sync.aligned.m8n8.x4.trans.shared.b16 {%0,%1,%2,%3}, [%4];" \
        : "=r"(r0), "=r"(r1), "=r"(r2), "=r"(r3) : "r"(a))

#define MMA_F16(c, a, b0, b1) \
    asm volatile("mma.sync.aligned.m16n8k16.row.col.f32.f16.f16.f32 " \
        "{%0,%1,%2,%3}, {%4,%5,%6,%7}, {%8,%9}, {%0,%1,%2,%3};" \
        : "+f"((c)[0]), "+f"((c)[1]), "+f"((c)[2]), "+f"((c)[3]) \
        : "r"((a)[0]), "r"((a)[1]), "r"((a)[2]), "r"((a)[3]), "r"(b0), "r"(b1))

#define CP16(dst, src) \
    asm volatile("cp.async.cg.shared.global [%0], [%1], 16;" :: "r"(dst), "l"(src))
#define CPCOMMIT() asm volatile("cp.async.commit_group;" ::: "memory")
#define CPWAIT(n)  asm volatile("cp.async.wait_group %0;" :: "n"(n) : "memory")

#define ONE2 0x3C003C00u   // half2(1.0, 1.0)

__device__ __forceinline__ uint32_t ex2h2(uint32_t x) {
    uint32_t r;
    asm("ex2.approx.f16x2 %0, %1;" : "=r"(r) : "r"(x));
    return r;
}
__device__ __forceinline__ uint32_t pack_h2(float a, float b) {
    __half2 h = __floats2half2_rn(a, b);
    return *(uint32_t*)&h;
}

// ---------------------------------------------------------------------------
// Fused prep: z<4 -> transpose weight widx to fp16 [N,K]; z==4 -> convert x.
// grid (32, 32, 5), block (32, 8).
// ---------------------------------------------------------------------------
__global__ void __launch_bounds__(256) prep_kernel(
    const float* __restrict__ x,
    const float* __restrict__ W0, const float* __restrict__ W1,
    const float* __restrict__ W2, const float* __restrict__ W3)
{
    const int widx = blockIdx.z;
    if (widx == 4) {
        // x conversion: 1024 blocks x 256 threads x 32 elems
        const int bid = blockIdx.y * 32 + blockIdx.x;
        const int tid = threadIdx.y * 32 + threadIdx.x;
#pragma unroll
        for (int i = 0; i < 8; i++) {
            size_t idx = ((size_t)bid * 2048 + i * 256 + tid) * 4;
            float4 v = *(const float4*)(x + idx);
            ((__half2*)(g_x16 + idx))[0] = __floats2half2_rn(v.x, v.y);
            ((__half2*)(g_x16 + idx))[1] = __floats2half2_rn(v.z, v.w);
        }
        return;
    }
    __shared__ float tile[32][33];
    const float* in = (widx == 0) ? W0 : (widx == 1) ? W1 : (widx == 2) ? W2 : W3;
    __half* o16 = (widx < 3) ? (g_w16 + (size_t)widx * 1024 * 1024) : g_wo16;
    int tx = threadIdx.x, ty = threadIdx.y;
    int xx = blockIdx.x * 32 + tx, y0 = blockIdx.y * 32;
#pragma unroll
    for (int j = 0; j < 32; j += 8) tile[ty + j][tx] = in[(size_t)(y0 + ty + j) * 1024 + xx];
    __syncthreads();
    int x2 = blockIdx.y * 32 + tx, y2 = blockIdx.x * 32;
#pragma unroll
    for (int j = 0; j < 32; j += 8)
        o16[(size_t)(y2 + ty + j) * 1024 + x2] = __float2half(tile[tx][ty + j]);
}

#define NT_K 32
#define GPL 10240          // one 128x40-fp16 plane (bytes)
#define GSTG (2 * GPL)     // 20480 per stage: A | B

// ---------------------------------------------------------------------------
// Unified fp16 GEMM, 1 MMA/tile: C = A @ B^T. Single fp16 A and B.
// 2-stage cp.async, 2 planes/stage (40KB total, 2 CTAs/SM).
// mode 0 (QKV, N=3072): scatter Q(prescaled)/K/V single fp16 [B,H,T,D].
// mode 1 (out, N=1024): fp32 row-major Cext.
// ---------------------------------------------------------------------------
__global__ void __launch_bounds__(256, 2) gemm16(
    const __half* __restrict__ Ap, const __half* __restrict__ Bp,
    float* __restrict__ Cext, const float* __restrict__ ls, int mode)
{
    extern __shared__ char gsm[];
    const uint32_t sb = smem_u32(gsm);
    const int tid = threadIdx.x;
    const int warp = tid >> 5, lane = tid & 31;
    const int bm = blockIdx.y * 128, bn = blockIdx.x * 128;
    const int wm = (warp >> 2) * 64, wn = (warp & 3) * 32;

    float acc[4][4][4];
#pragma unroll
    for (int i = 0; i < 4; i++)
#pragma unroll
        for (int j = 0; j < 4; j++)
#pragma unroll
            for (int r = 0; r < 4; r++) acc[i][j][r] = 0.f;

    const int lr = tid >> 1, lc = (tid & 1) << 4;
    const size_t aoff = (size_t)(bm + lr) * K_ + lc;
    const size_t boff = (size_t)(bn + lr) * K_ + lc;
    const uint32_t drow = sb + (uint32_t)lr * 80 + (uint32_t)lc * 2;

#define GISSUE(st, kt) do { \
    uint32_t d = drow + (uint32_t)(st) * GSTG; \
    size_t k0 = (size_t)(kt) * 32; \
    CP16(d,              Ap + aoff + k0); \
    CP16(d + 16,         Ap + aoff + k0 + 8); \
    CP16(d + GPL,        Bp + boff + k0); \
    CP16(d + GPL + 16,   Bp + boff + k0 + 8); \
} while (0)

    GISSUE(0, 0);
    CPCOMMIT();

    const uint32_t aAddr = (uint32_t)((wm + (lane & 15)) * 80 + (((lane >> 4) << 3)) * 2);
    const uint32_t bAddr = (uint32_t)(GPL + (wn + ((lane >> 4) << 3) + (lane & 7)) * 80 + ((lane & 8)) * 2);

    for (int kt = 0; kt < NT_K; ++kt) {
        {
            int nt = kt + 1;
            if (nt < NT_K) GISSUE(nt & 1, nt);
            CPCOMMIT();
        }
        CPWAIT(1);
        __syncthreads();
        const uint32_t stb = sb + (uint32_t)(kt & 1) * GSTG;

#pragma unroll
        for (int kk = 0; kk < 2; kk++) {
            const uint32_t ko = (uint32_t)(kk * 32);
            uint32_t ah[4][4];
#pragma unroll
            for (int i = 0; i < 4; i++) {
                uint32_t ad = stb + aAddr + (uint32_t)(i * 16 * 80) + ko;
                LDSM4(ah[i][0], ah[i][1], ah[i][2], ah[i][3], ad);
            }
#pragma unroll
            for (int jb = 0; jb < 2; jb++) {
                uint32_t bh[4];
                uint32_t bd = stb + bAddr + (uint32_t)(jb * 16 * 80) + ko;
                LDSM4(bh[0], bh[1], bh[2], bh[3], bd);
#pragma unroll
                for (int i = 0; i < 4; i++) {
                    MMA_F16(acc[i][2*jb],   ah[i], bh[0], bh[1]);
                    MMA_F16(acc[i][2*jb+1], ah[i], bh[2], bh[3]);
                }
            }
        }
        __syncthreads();
    }

    const int gr = lane >> 2, gc = (lane & 3) * 2;
    if (mode == 0) {
        const int sel = (bn + wn) >> 10;            // 0=Q 1=K 2=V (warp-constant)
        const int hh = ((bn + wn) >> 6) & 15;
        const float qs = (sel == 0) ? __expf(ls[hh]) * 0.125f * 1.4426950408889634f : 1.f;
        __half* Dst = (sel == 0) ? g_q16 : (sel == 1) ? g_k16 : g_v16;
#pragma unroll
        for (int i = 0; i < 4; i++)
#pragma unroll
            for (int j = 0; j < 4; j++) {
                int m0 = bm + wm + i * 16 + gr;
                int n0 = bn + wn + j * 8 + gc;
                int d = n0 & 63;
#pragma unroll
                for (int hrow = 0; hrow < 2; hrow++) {
                    int m = m0 + hrow * 8;
                    int b = m >> 11, t = m & (T_ - 1);
                    size_t idx = ((size_t)((b * H_ + hh) * T_ + t)) * D_ + d;
                    *(uint32_t*)(Dst + idx) =
                        pack_h2(acc[i][j][hrow*2] * qs, acc[i][j][hrow*2+1] * qs);
                }
            }
    } else {
#pragma unroll
        for (int i = 0; i < 4; i++)
#pragma unroll
            for (int j = 0; j < 4; j++) {
                int m0 = bm + wm + i * 16 + gr;
                int n0 = bn + wn + j * 8 + gc;
                *(float2*)&Cext[(size_t)m0 * N_ + n0] = make_float2(acc[i][j][0], acc[i][j][1]);
                *(float2*)&Cext[(size_t)(m0 + 8) * N_ + n0] = make_float2(acc[i][j][2], acc[i][j][3]);
            }
    }
}

// ---------------------------------------------------------------------------
// Flash attention (R14-best structure): 64-key 2-stage cp.async, f16x2 softmax,
// l via ones-column MMA. 256 threads, 128 q-rows/CTA. QK^T = 1 MMA; PV = 1 MMA.
// ---------------------------------------------------------------------------
#define AST 72
#define PL64  (64 * AST * 2)     // 9216
#define PL16  (16 * AST * 2)     // 2304
#define STAGE_B (2 * PL64)       // 18432: K | V
#define S_NULL  (2 * STAGE_B)    // 36864
#define S_NK  (S_NULL)
#define S_NV  (S_NULL + PL16)
#define S_ATT_TOTAL (S_NULL + 2*PL16)   // 41472

__global__ void __launch_bounds__(256, 2) attn_mma(
    const float* __restrict__ nullk, const float* __restrict__ nullv)
{
    extern __shared__ char sm[];
    const uint32_t sb = smem_u32(sm);
    const int bh = blockIdx.y, h = bh & 15;
    const int qblk = (T_ / 128 - 1) - blockIdx.x;   // longest first
    const int qbase = qblk * 128;
    const int tid = threadIdx.x, warp = tid >> 5, lane = tid & 31;
    const int wm = warp * 16;

    // null tiles: 16 x 64, row 0 real
    for (int i = tid; i < 1024; i += 256) {
        int r = i >> 6, d = i & 63;
        float kvk = (r == 0) ? nullk[h * 64 + d] : 0.f;
        float kvv = (r == 0) ? nullv[h * 64 + d] : 0.f;
        *(__half*)(sm + S_NK + (r * AST + d) * 2) = __float2half(kvk);
        *(__half*)(sm + S_NV + (r * AST + d) * 2) = __float2half(kvv);
    }

    // Q fragments: direct LDG from prescaled fp16 plane
    uint32_t qf[4][4];
    {
        const size_t qrow0 = (size_t)bh * T_ + qbase + wm + (lane >> 2);
        const int cc = (lane & 3) * 2;
#pragma unroll
        for (int kk = 0; kk < 4; kk++) {
#pragma unroll
            for (int rg = 0; rg < 4; rg++) {
                int roff = (rg & 1) * 8;
                int col = kk * 16 + cc + (rg >> 1) * 8;
                qf[kk][rg] = *(const uint32_t*)(g_q16 + (qrow0 + roff) * D_ + col);
            }
        }
    }

    float o[8][4];
#pragma unroll
    for (int j = 0; j < 8; j++)
#pragma unroll
        for (int r = 0; r < 4; r++) o[j][r] = 0.f;
    float lacc[4] = {0.f, 0.f, 0.f, 0.f};   // l via P @ ones

    const int qmin_w = qbase + wm;
    const int qmax_w = qbase + wm + 15;
    const int nkb = (qbase + 128) / 64;

    // K/V cp.async staging map: row=tid>>2 (0..63), col chunk=(tid&3)*16
    const int sr = tid >> 2, scol = (tid & 3) * 16;
    const uint32_t doff = (uint32_t)((sr * AST + scol) * 2);
    const size_t gbase0 = ((size_t)bh * T_ + sr) * D_ + scol;

#define AISS(st, kb_) do { \
    size_t base_ = gbase0 + (size_t)(kb_) * 64 * D_; \
    uint32_t d_ = sb + (uint32_t)(st) * STAGE_B + doff; \
    CP16(d_,              g_k16 + base_); \
    CP16(d_ + 16,         g_k16 + base_ + 8); \
    CP16(d_ + PL64,       g_v16 + base_); \
    CP16(d_ + PL64 + 16,  g_v16 + base_ + 8); \
} while (0)

    AISS(0, 0);
    CPCOMMIT();

    for (int kb = 0; kb < nkb; kb++) {
        __syncthreads();                 // everyone done reading the other stage
        if (kb + 1 < nkb) AISS((kb + 1) & 1, kb + 1);
        CPCOMMIT();
        CPWAIT(1);
        __syncthreads();                 // stage kb visible to all
        if (kb * 64 > qmax_w) continue;  // warp fully below diagonal
        const uint32_t stb = sb + (uint32_t)(kb & 1) * STAGE_B;

        // S = Qs K^T   (1 MMA per acc)
        float s[8][4];
#pragma unroll
        for (int j = 0; j < 8; j++)
#pragma unroll
            for (int r = 0; r < 4; r++) s[j][r] = 0.f;
#pragma unroll
        for (int kk = 0; kk < 4; kk++) {
#pragma unroll
            for (int jb = 0; jb < 4; jb++) {
                uint32_t kf[4];
                uint32_t bd = stb + (uint32_t)((jb * 16 + ((lane >> 4) << 3) + (lane & 7)) * AST
                            + kk * 16 + (lane & 8)) * 2;
                LDSM4(kf[0], kf[1], kf[2], kf[3], bd);
                MMA_F16(s[2*jb],   qf[kk], kf[0], kf[1]);
                MMA_F16(s[2*jb+1], qf[kk], kf[2], kf[3]);
            }
        }

        // causal mask (diagonal warp-block only)
        if (kb * 64 + 63 > qmin_w) {
            const int q0 = qmin_w + (lane >> 2), q1 = q0 + 8;
#pragma unroll
            for (int j = 0; j < 8; j++) {
                int c = kb * 64 + j * 8 + ((lane & 3) << 1);
                if (c     > q0) s[j][0] = -1e30f;
                if (c + 1 > q0) s[j][1] = -1e30f;
                if (c     > q1) s[j][2] = -1e30f;
                if (c + 1 > q1) s[j][3] = -1e30f;
            }
        }

        // P = exp2(S) in f16x2; l += P @ 1 (tensor pipe)
        uint32_t ph[4][4];
#pragma unroll
        for (int kk = 0; kk < 4; kk++) {
            ph[kk][0] = ex2h2(pack_h2(s[2*kk][0],   s[2*kk][1]));
            ph[kk][1] = ex2h2(pack_h2(s[2*kk][2],   s[2*kk][3]));
            ph[kk][2] = ex2h2(pack_h2(s[2*kk+1][0], s[2*kk+1][1]));
            ph[kk][3] = ex2h2(pack_h2(s[2*kk+1][2], s[2*kk+1][3]));
            MMA_F16(lacc, ph[kk], ONE2, ONE2);
        }

        // O += P V   (1 MMA per acc)
#pragma unroll
        for (int kk = 0; kk < 4; kk++) {
#pragma unroll
            for (int g = 0; g < 4; g++) {
                uint32_t vh[4];
                uint32_t vd = stb + PL64 + (uint32_t)((kk * 16 + (lane & 15)) * AST
                            + g * 16 + ((lane >> 4) << 3)) * 2;
                LDSM4T(vh[0], vh[1], vh[2], vh[3], vd);
                MMA_F16(o[2*g],   ph[kk], vh[0], vh[1]);
                MMA_F16(o[2*g+1], ph[kk], vh[2], vh[3]);
            }
        }
    }

    // null-KV block (16 padded cols, col 0 real)
    {
        float s[2][4];
#pragma unroll
        for (int j = 0; j < 2; j++)
#pragma unroll
            for (int r = 0; r < 4; r++) s[j][r] = 0.f;
#pragma unroll
        for (int kk = 0; kk < 4; kk++) {
            uint32_t kf[4];
            uint32_t bd = sb + S_NK + (uint32_t)((((lane >> 4) << 3) + (lane & 7)) * AST
                        + kk * 16 + (lane & 8)) * 2;
            LDSM4(kf[0], kf[1], kf[2], kf[3], bd);
            MMA_F16(s[0], qf[kk], kf[0], kf[1]);
            MMA_F16(s[1], qf[kk], kf[2], kf[3]);
        }
#pragma unroll
        for (int j = 0; j < 2; j++) {
            int c = j * 8 + ((lane & 3) << 1);
            if (c != 0) s[j][0] = -1e30f;
            s[j][1] = -1e30f;
            if (c != 0) s[j][2] = -1e30f;
            s[j][3] = -1e30f;
        }
        uint32_t ph[4];
        ph[0] = ex2h2(pack_h2(s[0][0], s[0][1]));
        ph[1] = ex2h2(pack_h2(s[0][2], s[0][3]));
        ph[2] = ex2h2(pack_h2(s[1][0], s[1][1]));
        ph[3] = ex2h2(pack_h2(s[1][2], s[1][3]));
        MMA_F16(lacc, ph, ONE2, ONE2);
#pragma unroll
        for (int g = 0; g < 4; g++) {
            uint32_t vh[4];
            uint32_t vd = sb + S_NV + (uint32_t)((lane & 15) * AST + g * 16 + ((lane >> 4) << 3)) * 2;
            LDSM4T(vh[0], vh[1], vh[2], vh[3], vd);
            MMA_F16(o[2*g],   ph, vh[0], vh[1]);
            MMA_F16(o[2*g+1], ph, vh[2], vh[3]);
        }
    }

    // finalize: l comes straight from lacc (row sums, replicated per quad)
    const float i0 = 1.f / lacc[0], i1 = 1.f / lacc[2];
    const int b = bh >> 4;
    const int t0 = qbase + wm + (lane >> 2), t1 = t0 + 8;
    const int cb = h * 64 + ((lane & 3) << 1);
#pragma unroll
    for (int j = 0; j < 8; j++) {
        int cc = cb + j * 8;
        *(uint32_t*)(g_y16 + (size_t)(b * T_ + t0) * C_ + cc) = pack_h2(o[j][0] * i0, o[j][1] * i0);
        *(uint32_t*)(g_y16 + (size_t)(b * T_ + t1) * C_ + cc) = pack_h2(o[j][2] * i1, o[j][3] * i1);
    }
}

// ---------------------------------------------------------------------------
// kernel_launch
// Inputs: x, Wq, Wk, Wv, Wo, null_k, null_v, logit_scale
// ---------------------------------------------------------------------------
extern "C" void kernel_launch(void* const* d_in, const int* in_sizes, int n_in,
                              void* d_out, int out_size) {
    const float* x  = (const float*)d_in[0];
    const float* Wq = (const float*)d_in[1];
    const float* Wk = (const float*)d_in[2];
    const float* Wv = (const float*)d_in[3];
    const float* Wo = (const float*)d_in[4];
    const float* nk = (const float*)d_in[5];
    const float* nv = (const float*)d_in[6];
    const float* ls = (const float*)d_in[7];
    float* out = (float*)d_out;

    __half *x16, *y16, *w16, *wo16;
    cudaGetSymbolAddress((void**)&x16, g_x16);
    cudaGetSymbolAddress((void**)&y16, g_y16);
    cudaGetSymbolAddress((void**)&w16, g_w16);
    cudaGetSymbolAddress((void**)&wo16, g_wo16);

    const int GEMM_SMEM = 2 * GSTG;       // 40960
    cudaFuncSetAttribute(gemm16, cudaFuncAttributeMaxDynamicSharedMemorySize, GEMM_SMEM);
    cudaFuncSetAttribute(attn_mma, cudaFuncAttributeMaxDynamicSharedMemorySize, S_ATT_TOTAL);

    prep_kernel<<<dim3(32, 32, 5), dim3(32, 8)>>>(x, Wq, Wk, Wv, Wo);

    gemm16<<<dim3(24, 64), 256, GEMM_SMEM>>>(x16, w16, nullptr, ls, 0);

    attn_mma<<<dim3(T_ / 128, B_ * H_), 256, S_ATT_TOTAL>>>(nk, nv);

    gemm16<<<dim3(8, 64), 256, GEMM_SMEM>>>(y16, wo16, out, ls, 1);
}